// round 1
// baseline (speedup 1.0000x reference)
#include <cuda_runtime.h>

// InterConv: B=2048, F=39, E=64, C=64, P=741
// out[b, c*P + p] = relu( dot(x[b,ii[p]], Wi[c]) + dot(x[b,jj[p]], Wj[c]) + bias[c] )
// Factorization: U[f,c] = x[f]·Wi[c] + bias[c];  V[f,c] = x[f]·Wj[c]
//                out[c*P+p] = relu(U[ii[p],c] + V[jj[p],c])

#define FN 39
#define EN 64
#define CN 64
#define PN 741            // 39*38/2
#define OUTB (CN * PN)    // 47424 floats per batch
#define THREADS 256

// smem float offsets
#define XS_OFF   0                   // x: 39*64 = 2496
#define WI_OFF   (XS_OFF + FN*EN)    // Wi padded [c][68]: 64*68 = 4352
#define WJ_OFF   (WI_OFF + CN*68)    // Wj padded: 4352
#define UC_OFF   (WJ_OFF + CN*68)    // U transposed [c][41]: 2624
#define VC_OFF   (UC_OFF + CN*41)    // V transposed: 2624
#define TAB_OFF  (VC_OFF + CN*41)    // u16 pair table (741 entries = 371 floats)
#define SMEM_FLOATS (TAB_OFF + 376)
#define SMEM_BYTES  (SMEM_FLOATS * 4)

extern __shared__ float smem[];

__global__ void __launch_bounds__(THREADS, 3)
interconv_kernel(const float* __restrict__ x,
                 const float* __restrict__ W,
                 const float* __restrict__ bias,
                 float* __restrict__ out)
{
    float* xs = smem + XS_OFF;
    float* Wi = smem + WI_OFF;
    float* Wj = smem + WJ_OFF;
    float* Uc = smem + UC_OFF;
    float* Vc = smem + VC_OFF;
    unsigned short* tab = (unsigned short*)(smem + TAB_OFF);

    const int tid = threadIdx.x;
    const long long b = blockIdx.x;
    const float* xb = x + b * (long long)(FN * EN);

    // ---- Phase 0: cooperative loads -------------------------------------
    // x: coalesced
    for (int idx = tid; idx < FN * EN; idx += THREADS)
        xs[idx] = xb[idx];

    // W layout in gmem: W[c][0][k][e] -> flat c*128 + k*64 + e
    // smem: Wi[c*68+e], Wj[c*68+e]  (pad 68 -> conflict-free LDS.128 with lane=c)
    for (int idx = tid; idx < CN * EN; idx += THREADS) {
        int c = idx >> 6, e = idx & 63;
        Wi[c * 68 + e] = W[c * 128 + e];
        Wj[c * 68 + e] = W[c * 128 + 64 + e];
    }

    // pair table: np.triu_indices(F,1) row-major order
    for (int p = tid; p < PN; p += THREADS) {
        int i = 0, rem = p;
        while (rem >= FN - 1 - i) { rem -= FN - 1 - i; i++; }
        int j = i + 1 + rem;
        tab[p] = (unsigned short)((i << 8) | j);
    }
    __syncthreads();

    // ---- Phase 1: U = x @ Wi^T + b, V = x @ Wj^T ------------------------
    // thread = (c = tid&63, fgroup = tid>>6); each thread covers f = fg, fg+4, ...
    {
        const int c  = tid & 63;
        const int fg = tid >> 6;
        const float bc = __ldg(bias + c);

        float au[10], av[10];
        #pragma unroll
        for (int k = 0; k < 10; k++) { au[k] = 0.f; av[k] = 0.f; }

        const float4* xs4 = (const float4*)xs;       // [f][16]
        const float4* Wi4 = (const float4*)Wi;       // [c][17]
        const float4* Wj4 = (const float4*)Wj;

        #pragma unroll
        for (int e4 = 0; e4 < 16; e4++) {
            float4 wi = Wi4[c * 17 + e4];
            float4 wj = Wj4[c * 17 + e4];
            #pragma unroll
            for (int k = 0; k < 10; k++) {
                int f = fg + 4 * k;
                if (f < FN) {
                    float4 xv = xs4[f * 16 + e4];
                    au[k] += xv.x * wi.x + xv.y * wi.y + xv.z * wi.z + xv.w * wi.w;
                    av[k] += xv.x * wj.x + xv.y * wj.y + xv.z * wj.z + xv.w * wj.w;
                }
            }
        }
        #pragma unroll
        for (int k = 0; k < 10; k++) {
            int f = fg + 4 * k;
            if (f < FN) {
                Uc[c * 41 + f] = au[k] + bc;   // bias folded into U
                Vc[c * 41 + f] = av[k];
            }
        }
    }
    __syncthreads();

    // ---- Phase 2: expansion + relu + coalesced store --------------------
    // out flat per batch: n = c*741 + p
    float* outb = out + b * (long long)OUTB;
    int n = tid;
    int c = 0, p = tid;            // tid < 256 < 741, so c starts at 0
    while (n < OUTB) {
        unsigned int t = tab[p];
        float u = Uc[c * 41 + (t >> 8)];
        float v = Vc[c * 41 + (t & 255)];
        float val = u + v;
        outb[n] = val > 0.f ? val : 0.f;
        n += THREADS;
        p += THREADS;
        if (p >= PN) { p -= PN; c++; }
    }
}

extern "C" void kernel_launch(void* const* d_in, const int* in_sizes, int n_in,
                              void* d_out, int out_size)
{
    const float* x    = (const float*)d_in[0];
    const float* W    = (const float*)d_in[1];
    const float* bias = (const float*)d_in[2];
    float* out = (float*)d_out;

    const int B = in_sizes[0] / (FN * EN);   // 2048

    cudaFuncSetAttribute(interconv_kernel,
                         cudaFuncAttributeMaxDynamicSharedMemorySize, SMEM_BYTES);
    interconv_kernel<<<B, THREADS, SMEM_BYTES>>>(x, W, bias, out);
}

// round 2
// speedup vs baseline: 1.0063x; 1.0063x over previous
#include <cuda_runtime.h>

// InterConv: B=2048, F=39, E=64, C=64, P=741
// out[b, c*P + p] = relu( dot(x[b,ii[p]], Wi[c]) + dot(x[b,jj[p]], Wj[c]) + bias[c] )
// Factorization: U[f,c] = x[f]·Wi[c] + bias[c];  V[f,c] = x[f]·Wj[c]
//                out[c*P+p] = relu(U[ii[p],c] + V[jj[p],c])

#define FN 39
#define EN 64
#define CN 64
#define PN 741            // 39*38/2
#define OUTB (CN * PN)    // 47424 floats per batch
#define THREADS 256

// smem float offsets
#define XS_OFF   0                   // x: 39*64 = 2496
#define WI_OFF   (XS_OFF + FN*EN)    // Wi padded [c][68]: 64*68 = 4352
#define WJ_OFF   (WI_OFF + CN*68)    // Wj padded: 4352
#define UC_OFF   (WJ_OFF + CN*68)    // U transposed [c][41]: 2624
#define VC_OFF   (UC_OFF + CN*41)    // V transposed: 2624
#define TAB_OFF  (VC_OFF + CN*41)    // u16 pair table (741 entries = 371 floats)
#define SMEM_FLOATS (TAB_OFF + 376)
#define SMEM_BYTES  (SMEM_FLOATS * 4)

extern __shared__ float smem[];

__global__ void __launch_bounds__(THREADS, 3)
interconv_kernel(const float* __restrict__ x,
                 const float* __restrict__ W,
                 const float* __restrict__ bias,
                 float* __restrict__ out)
{
    float* xs = smem + XS_OFF;
    float* Wi = smem + WI_OFF;
    float* Wj = smem + WJ_OFF;
    float* Uc = smem + UC_OFF;
    float* Vc = smem + VC_OFF;
    unsigned short* tab = (unsigned short*)(smem + TAB_OFF);

    const int tid = threadIdx.x;
    const long long b = blockIdx.x;
    const float* xb = x + b * (long long)(FN * EN);

    // ---- Phase 0: cooperative loads -------------------------------------
    // x: coalesced
    for (int idx = tid; idx < FN * EN; idx += THREADS)
        xs[idx] = xb[idx];

    // W layout in gmem: W[c][0][k][e] -> flat c*128 + k*64 + e
    // smem: Wi[c*68+e], Wj[c*68+e]  (pad 68 -> conflict-free LDS.128 with lane=c)
    for (int idx = tid; idx < CN * EN; idx += THREADS) {
        int c = idx >> 6, e = idx & 63;
        Wi[c * 68 + e] = W[c * 128 + e];
        Wj[c * 68 + e] = W[c * 128 + 64 + e];
    }

    // pair table: np.triu_indices(F,1) row-major order
    for (int p = tid; p < PN; p += THREADS) {
        int i = 0, rem = p;
        while (rem >= FN - 1 - i) { rem -= FN - 1 - i; i++; }
        int j = i + 1 + rem;
        tab[p] = (unsigned short)((i << 8) | j);
    }
    __syncthreads();

    // ---- Phase 1: U = x @ Wi^T + b, V = x @ Wj^T ------------------------
    // thread = (c = tid&63, fgroup = tid>>6); each thread covers f = fg, fg+4, ...
    {
        const int c  = tid & 63;
        const int fg = tid >> 6;
        const float bc = __ldg(bias + c);

        float au[10], av[10];
        #pragma unroll
        for (int k = 0; k < 10; k++) { au[k] = 0.f; av[k] = 0.f; }

        const float4* xs4 = (const float4*)xs;       // [f][16]
        const float4* Wi4 = (const float4*)Wi;       // [c][17]
        const float4* Wj4 = (const float4*)Wj;

        #pragma unroll
        for (int e4 = 0; e4 < 16; e4++) {
            float4 wi = Wi4[c * 17 + e4];
            float4 wj = Wj4[c * 17 + e4];
            #pragma unroll
            for (int k = 0; k < 10; k++) {
                int f = fg + 4 * k;
                if (f < FN) {
                    float4 xv = xs4[f * 16 + e4];
                    au[k] += xv.x * wi.x + xv.y * wi.y + xv.z * wi.z + xv.w * wi.w;
                    av[k] += xv.x * wj.x + xv.y * wj.y + xv.z * wj.z + xv.w * wj.w;
                }
            }
        }
        #pragma unroll
        for (int k = 0; k < 10; k++) {
            int f = fg + 4 * k;
            if (f < FN) {
                Uc[c * 41 + f] = au[k] + bc;   // bias folded into U
                Vc[c * 41 + f] = av[k];
            }
        }
    }
    __syncthreads();

    // ---- Phase 2: expansion + relu + coalesced store --------------------
    // out flat per batch: n = c*741 + p
    float* outb = out + b * (long long)OUTB;
    int n = tid;
    int c = 0, p = tid;            // tid < 256 < 741, so c starts at 0
    while (n < OUTB) {
        unsigned int t = tab[p];
        float u = Uc[c * 41 + (t >> 8)];
        float v = Vc[c * 41 + (t & 255)];
        float val = u + v;
        outb[n] = val > 0.f ? val : 0.f;
        n += THREADS;
        p += THREADS;
        if (p >= PN) { p -= PN; c++; }
    }
}

extern "C" void kernel_launch(void* const* d_in, const int* in_sizes, int n_in,
                              void* d_out, int out_size)
{
    const float* x    = (const float*)d_in[0];
    const float* W    = (const float*)d_in[1];
    const float* bias = (const float*)d_in[2];
    float* out = (float*)d_out;

    const int B = in_sizes[0] / (FN * EN);   // 2048

    cudaFuncSetAttribute(interconv_kernel,
                         cudaFuncAttributeMaxDynamicSharedMemorySize, SMEM_BYTES);
    interconv_kernel<<<B, THREADS, SMEM_BYTES>>>(x, W, bias, out);
}

// round 3
// speedup vs baseline: 1.1938x; 1.1863x over previous
#include <cuda_runtime.h>

// InterConv: B=2048, F=39, E=64, C=64, P=741
// out[b, c*P + p] = relu( dot(x[b,ii[p]], Wi[c]) + dot(x[b,jj[p]], Wj[c]) + bias[c] )
// Factorization: U[f,c] = x[f]·Wi[c] + bias[c];  V[f,c] = x[f]·Wj[c]
//                out[c*P+p] = relu(U[ii[p],c] + V[jj[p],c])

#define FN 39
#define EN 64
#define CN 64
#define PN 741            // 39*38/2
#define OUTB (CN * PN)    // 47424 floats per batch
#define THREADS 256

// smem float offsets
#define XS_OFF   0                    // x padded to 40 rows: 40*64 = 2560
#define WI_OFF   (XS_OFF + 40*EN)     // Wi padded [c][68]: 4352
#define WJ_OFF   (WI_OFF + CN*68)     // Wj padded: 4352
#define UC_OFF   (WJ_OFF + CN*68)     // U transposed [c][41]: 2624
#define VC_OFF   (UC_OFF + CN*41)     // V transposed: 2624
#define TAB_OFF  (VC_OFF + CN*41)     // u32 combined byte-offset table (741 entries)
#define SMEM_FLOATS (TAB_OFF + 744)
#define SMEM_BYTES  (SMEM_FLOATS * 4)

// packed fp32x2 FMA (Blackwell-only; exact fp32 semantics, 2x FFMA throughput)
#define FMA_F32X2(acc, a, b) \
    asm("fma.rn.f32x2 %0, %1, %2, %0;" : "+l"(acc) : "l"(a), "l"(b))

extern __shared__ float smem[];

__global__ void __launch_bounds__(THREADS, 3)
interconv_kernel(const float* __restrict__ x,
                 const float* __restrict__ W,
                 const float* __restrict__ bias,
                 float* __restrict__ out)
{
    float* xs = smem + XS_OFF;
    float* Wi = smem + WI_OFF;
    float* Wj = smem + WJ_OFF;
    float* Uc = smem + UC_OFF;
    float* Vc = smem + VC_OFF;
    unsigned* tab = (unsigned*)(smem + TAB_OFF);

    const int tid = threadIdx.x;
    const long long b = blockIdx.x;
    const float* xb = x + b * (long long)(FN * EN);

    // ---- Phase 0: cooperative loads -------------------------------------
    for (int idx = tid; idx < FN * EN; idx += THREADS)
        xs[idx] = xb[idx];
    if (tid < EN)                       // zero pad row f=39 (lets phase 1 run unguarded)
        xs[FN * EN + tid] = 0.f;

    // W gmem layout: flat c*128 + k*64 + e ; smem padded stride 68
    for (int idx = tid; idx < CN * EN; idx += THREADS) {
        int c = idx >> 6, e = idx & 63;
        Wi[c * 68 + e] = W[c * 128 + e];
        Wj[c * 68 + e] = W[c * 128 + 64 + e];
    }

    // pair table: np.triu_indices(F,1) row-major; store combined BYTE offsets:
    // low 16 bits = i*4 (offset into Uc row), high 16 bits = j*4 (offset into Vc row)
    for (int p = tid; p < PN; p += THREADS) {
        int i = 0, rem = p;
        while (rem >= FN - 1 - i) { rem -= FN - 1 - i; i++; }
        int j = i + 1 + rem;
        tab[p] = (unsigned)(i * 4) | ((unsigned)(j * 4) << 16);
    }
    __syncthreads();

    // ---- Phase 1: U = x @ Wi^T + b, V = x @ Wj^T  (f32x2 packed) --------
    {
        const int c  = tid & 63;
        const int fg = tid >> 6;

        unsigned long long au[10], av[10];
        #pragma unroll
        for (int k = 0; k < 10; k++) { au[k] = 0ull; av[k] = 0ull; }

        const ulonglong2* xs2 = (const ulonglong2*)xs;   // [f][16] in 16B units
        const ulonglong2* Wi2 = (const ulonglong2*)Wi;   // [c][17]
        const ulonglong2* Wj2 = (const ulonglong2*)Wj;

        #pragma unroll
        for (int e4 = 0; e4 < 16; e4++) {
            ulonglong2 wi = Wi2[c * 17 + e4];
            ulonglong2 wj = Wj2[c * 17 + e4];
            #pragma unroll
            for (int k = 0; k < 10; k++) {
                ulonglong2 xv = xs2[(fg + 4 * k) * 16 + e4];  // f=39 row is zeros
                FMA_F32X2(au[k], xv.x, wi.x);
                FMA_F32X2(au[k], xv.y, wi.y);
                FMA_F32X2(av[k], xv.x, wj.x);
                FMA_F32X2(av[k], xv.y, wj.y);
            }
        }

        const float bc = __ldg(bias + c);
        #pragma unroll
        for (int k = 0; k < 10; k++) {
            int f = fg + 4 * k;                 // f<=39; f=39 lands in row pad (stride 41)
            float ulo = __uint_as_float((unsigned)au[k]);
            float uhi = __uint_as_float((unsigned)(au[k] >> 32));
            float vlo = __uint_as_float((unsigned)av[k]);
            float vhi = __uint_as_float((unsigned)(av[k] >> 32));
            Uc[c * 41 + f] = ulo + uhi + bc;    // bias folded into U
            Vc[c * 41 + f] = vlo + vhi;
        }
    }
    __syncthreads();

    // ---- Phase 2: expansion + relu, warp-per-c --------------------------
    // out flat per batch: n = c*741 + p.  Each warp owns c = cc*8 + warp_id.
    // p0 = (-741*c) mod 32 = (27c)&31 makes main-loop stores 128B-aligned.
    const int lane = tid & 31;
    const int wrp  = tid >> 5;
    float* outb = out + b * (long long)OUTB;

    #pragma unroll 1
    for (int cc = 0; cc < 8; cc++) {
        const int c = cc * 8 + wrp;
        const char* bu = (const char*)(Uc + c * 41);
        const char* bv = (const char*)(Vc + c * 41);
        float* po = outb + c * PN;
        const int p0 = (27 * c) & 31;

        // head: p in [0, p0)
        if (lane < p0) {
            unsigned t = tab[lane];
            float u = *(const float*)(bu + (t & 0xFFFFu));
            float v = *(const float*)(bv + (t >> 16));
            po[lane] = fmaxf(u + v, 0.f);
        }

        const unsigned* tb = tab + p0;
        float* po2 = po + p0;

        // main: 22 full warp-iterations, immediate offsets, aligned stores
        #pragma unroll
        for (int it = 0; it < 22; it++) {
            unsigned t = tb[it * 32 + lane];
            float u = *(const float*)(bu + (t & 0xFFFFu));
            float v = *(const float*)(bv + (t >> 16));
            po2[it * 32 + lane] = fmaxf(u + v, 0.f);
        }

        // tail: p in [p0+704, 741)  (6..37 elements -> two masked iterations)
        int p = p0 + 704 + lane;
        if (p < PN) {
            unsigned t = tab[p];
            float u = *(const float*)(bu + (t & 0xFFFFu));
            float v = *(const float*)(bv + (t >> 16));
            po[p] = fmaxf(u + v, 0.f);
        }
        p += 32;
        if (p < PN) {
            unsigned t = tab[p];
            float u = *(const float*)(bu + (t & 0xFFFFu));
            float v = *(const float*)(bv + (t >> 16));
            po[p] = fmaxf(u + v, 0.f);
        }
    }
}

extern "C" void kernel_launch(void* const* d_in, const int* in_sizes, int n_in,
                              void* d_out, int out_size)
{
    const float* x    = (const float*)d_in[0];
    const float* W    = (const float*)d_in[1];
    const float* bias = (const float*)d_in[2];
    float* out = (float*)d_out;

    const int B = in_sizes[0] / (FN * EN);   // 2048

    cudaFuncSetAttribute(interconv_kernel,
                         cudaFuncAttributeMaxDynamicSharedMemorySize, SMEM_BYTES);
    interconv_kernel<<<B, THREADS, SMEM_BYTES>>>(x, W, bias, out);
}

// round 4
// speedup vs baseline: 1.5754x; 1.3197x over previous
#include <cuda_runtime.h>

// InterConv: B=2048, F=39, E=64, C=64, P=741
// out[b, c*P + p] = relu( dot(x[b,ii[p]], Wi[c]) + dot(x[b,jj[p]], Wj[c]) + bias[c] )
// Factorization: U[f,c] = x[f]·Wi[c] + bias[c];  V[f,c] = x[f]·Wj[c]
//                out[c*P+p] = relu(U[ii[p],c] + V[jj[p],c])
//
// smem overlay (45.3 KB -> 4 CTAs/SM):
//   phase 0/1: A = xs [0,2624)     B = Wi [2624,6976) + Wj [6976,11328)
//   phase 2:   A = Uc [0,2624)     B = Vc [2624,5248) + tab [5248,5992)

#define FN 39
#define EN 64
#define CN 64
#define PN 741            // 39*38/2
#define OUTB (CN * PN)    // 47424 floats per batch
#define THREADS 256

#define A_OFF 0
#define B_OFF 2624
#define SMEM_FLOATS 11328
#define SMEM_BYTES  (SMEM_FLOATS * 4)

// packed fp32x2 FMA (Blackwell; exact fp32 semantics, 2x FFMA throughput)
#define FMA_F32X2(acc, a, b) \
    asm("fma.rn.f32x2 %0, %1, %2, %0;" : "+l"(acc) : "l"(a), "l"(b))

extern __shared__ float smem[];

__global__ void __launch_bounds__(THREADS, 4)
interconv_kernel(const float* __restrict__ x,
                 const float* __restrict__ W,
                 const float* __restrict__ bias,
                 float* __restrict__ out)
{
    const int tid = threadIdx.x;
    const long long b = blockIdx.x;

    // ---- Phase 0: stage x and W (float4) ---------------------------------
    {
        float4* xs4 = (float4*)(smem + A_OFF);
        const float4* xb4 = (const float4*)(x + b * (long long)(FN * EN));
        #pragma unroll
        for (int it = 0; it < 3; it++) {
            int idx = tid + it * THREADS;
            if (idx < (FN * EN) / 4) xs4[idx] = xb4[idx];
        }
        if (tid < EN)                              // zero pad row f=39
            smem[A_OFF + FN * EN + tid] = 0.f;

        // W gmem: [c][128] floats (k=0 -> Wi, k=1 -> Wj); smem stride 17 float4
        float4* Wi4 = (float4*)(smem + B_OFF);
        float4* Wj4 = Wi4 + CN * 17;
        const float4* Wg4 = (const float4*)W;
        #pragma unroll
        for (int it = 0; it < 8; it++) {
            int idx = tid + it * THREADS;          // 2048 float4 total
            int c = idx >> 5, q = idx & 31;
            float4 w = Wg4[idx];
            if (q < 16) Wi4[c * 17 + q] = w;
            else        Wj4[c * 17 + (q - 16)] = w;
        }
    }
    __syncthreads();

    // ---- Phase 1: U = x @ Wi^T + b, V = x @ Wj^T  (f32x2, regs only) -----
    const int c  = tid & 63;
    const int fg = tid >> 6;

    unsigned long long au[10], av[10];
    #pragma unroll
    for (int k = 0; k < 10; k++) { au[k] = 0ull; av[k] = 0ull; }

    {
        const ulonglong2* xs2 = (const ulonglong2*)(smem + A_OFF);   // [f][16B-units x16]
        const ulonglong2* Wi2 = (const ulonglong2*)(smem + B_OFF);   // [c][17]
        const ulonglong2* Wj2 = Wi2 + CN * 17;

        #pragma unroll
        for (int e4 = 0; e4 < 16; e4++) {
            ulonglong2 wi = Wi2[c * 17 + e4];
            ulonglong2 wj = Wj2[c * 17 + e4];
            #pragma unroll
            for (int k = 0; k < 10; k++) {
                ulonglong2 xv = xs2[(fg + 4 * k) * 16 + e4];  // f=39 row is zeros
                FMA_F32X2(au[k], xv.x, wi.x);
                FMA_F32X2(au[k], xv.y, wi.y);
                FMA_F32X2(av[k], xv.x, wj.x);
                FMA_F32X2(av[k], xv.y, wj.y);
            }
        }
    }
    __syncthreads();   // all xs/W reads done; safe to overlay

    // ---- Phase 1b: write Uc/Vc (transposed, stride 41) + build tab ------
    float* Uc = smem + A_OFF;                 // [c][41]
    float* Vc = smem + B_OFF;                 // [c][41]
    unsigned* tab = (unsigned*)(smem + B_OFF + CN * 41);

    {
        const float bc = __ldg(bias + c);
        #pragma unroll
        for (int k = 0; k < 10; k++) {
            int f = fg + 4 * k;               // f<=39; f=39 lands in row pad
            float ulo = __uint_as_float((unsigned)au[k]);
            float uhi = __uint_as_float((unsigned)(au[k] >> 32));
            float vlo = __uint_as_float((unsigned)av[k]);
            float vhi = __uint_as_float((unsigned)(av[k] >> 32));
            Uc[c * 41 + f] = ulo + uhi + bc;  // bias folded into U
            Vc[c * 41 + f] = vlo + vhi;
        }
        // pair table: np.triu_indices(F,1) row-major; byte offsets (i*4 | j*4<<16)
        for (int p = tid; p < PN; p += THREADS) {
            int i = 0, rem = p;
            while (rem >= FN - 1 - i) { rem -= FN - 1 - i; i++; }
            int j = i + 1 + rem;
            tab[p] = (unsigned)(i * 4) | ((unsigned)(j * 4) << 16);
        }
    }
    __syncthreads();

    // ---- Phase 2: expansion + relu, warp-per-c, aligned streaming stores -
    // out flat per batch: n = c2*741 + p.  p0 = (27*c2)&31 aligns main loop.
    const int lane = tid & 31;
    const int wrp  = tid >> 5;
    float* outb = out + b * (long long)OUTB;

    #pragma unroll 1
    for (int cc = 0; cc < 8; cc++) {
        const int c2 = cc * 8 + wrp;
        const char* bu = (const char*)(Uc + c2 * 41);
        const char* bv = (const char*)(Vc + c2 * 41);
        float* po = outb + c2 * PN;
        const int p0 = (27 * c2) & 31;

        // head: p in [0, p0)
        if (lane < p0) {
            unsigned t = tab[lane];
            float u = *(const float*)(bu + (t & 0xFFFFu));
            float v = *(const float*)(bv + (t >> 16));
            __stcs(po + lane, fmaxf(u + v, 0.f));
        }

        const unsigned* tb = tab + p0;
        float* po2 = po + p0;

        // main: 22 full warp-iterations, immediate offsets, 128B-aligned stores
        #pragma unroll
        for (int it = 0; it < 22; it++) {
            unsigned t = tb[it * 32 + lane];
            float u = *(const float*)(bu + (t & 0xFFFFu));
            float v = *(const float*)(bv + (t >> 16));
            __stcs(po2 + it * 32 + lane, fmaxf(u + v, 0.f));
        }

        // tail: p in [p0+704, 741)
        int p = p0 + 704 + lane;
        if (p < PN) {
            unsigned t = tab[p];
            float u = *(const float*)(bu + (t & 0xFFFFu));
            float v = *(const float*)(bv + (t >> 16));
            __stcs(po + p, fmaxf(u + v, 0.f));
        }
        p += 32;
        if (p < PN) {
            unsigned t = tab[p];
            float u = *(const float*)(bu + (t & 0xFFFFu));
            float v = *(const float*)(bv + (t >> 16));
            __stcs(po + p, fmaxf(u + v, 0.f));
        }
    }
}

extern "C" void kernel_launch(void* const* d_in, const int* in_sizes, int n_in,
                              void* d_out, int out_size)
{
    const float* x    = (const float*)d_in[0];
    const float* W    = (const float*)d_in[1];
    const float* bias = (const float*)d_in[2];
    float* out = (float*)d_out;

    const int B = in_sizes[0] / (FN * EN);   // 2048

    cudaFuncSetAttribute(interconv_kernel,
                         cudaFuncAttributeMaxDynamicSharedMemorySize, SMEM_BYTES);
    interconv_kernel<<<B, THREADS, SMEM_BYTES>>>(x, W, bias, out);
}